// round 1
// baseline (speedup 1.0000x reference)
#include <cuda_runtime.h>
#include <math.h>

#define D   768
#define F   3072
#define SEQ 2048
#define BAT 2
#define NH  12
#define HD  64
#define NROW  (BAT*SEQ)   // 4096
#define NHEAD (BAT*NH)    // 24

// ---------------- scratch (device globals: no allocations allowed) ----------
__device__ float g_h1[NROW*D];
__device__ float g_q [NROW*D];
__device__ float g_k [NROW*D];
__device__ float g_v [NROW*D];
__device__ float g_energy[(size_t)NHEAD*SEQ*SEQ];   // 402 MB
__device__ float g_ctx[NROW*D];
__device__ float g_x2 [NROW*D];
__device__ float g_h2 [NROW*D];
__device__ float g_mlp[(size_t)NROW*F];

// ---------------- LayerNorm: 1 block / row, 256 thr, 3 elems/thr ------------
__global__ void ln_kernel(const float* __restrict__ x, const float* __restrict__ g,
                          const float* __restrict__ be, float* __restrict__ out)
{
    __shared__ float sh[16];
    int row = blockIdx.x, t = threadIdx.x;
    const float* xr = x + (size_t)row * D;
    float v0 = xr[t], v1 = xr[t + 256], v2 = xr[t + 512];
    float s  = v0 + v1 + v2;
    float sq = v0*v0 + v1*v1 + v2*v2;
    #pragma unroll
    for (int o = 16; o; o >>= 1) {
        s  += __shfl_down_sync(0xffffffffu, s,  o);
        sq += __shfl_down_sync(0xffffffffu, sq, o);
    }
    int lane = t & 31, w = t >> 5;
    if (lane == 0) { sh[w] = s; sh[8 + w] = sq; }
    __syncthreads();
    if (t < 8) {
        s = sh[t]; sq = sh[8 + t];
        #pragma unroll
        for (int o = 4; o; o >>= 1) {
            s  += __shfl_down_sync(0xffu, s,  o);
            sq += __shfl_down_sync(0xffu, sq, o);
        }
        if (t == 0) {
            float mu  = s * (1.0f / 768.0f);
            float var = sq * (1.0f / 768.0f) - mu * mu;
            sh[0] = mu; sh[1] = rsqrtf(var + 1e-5f);
        }
    }
    __syncthreads();
    float mu = sh[0], r = sh[1];
    float* orow = out + (size_t)row * D;
    orow[t]       = (v0 - mu) * r * g[t]       + be[t];
    orow[t + 256] = (v1 - mu) * r * g[t + 256] + be[t + 256];
    orow[t + 512] = (v2 - mu) * r * g[t + 512] + be[t + 512];
}

// ---------------- energy = q k^T / 8, per head (K=64) ----------------------
// 128x128 output tile per block, K chunked by 32. grid: (16,16,24)
__global__ void energy_kernel(const float* __restrict__ q, const float* __restrict__ k,
                              float* __restrict__ e)
{
    __shared__ float Qs[32][128];
    __shared__ float Ks[32][128];
    int z = blockIdx.z;               // b*NH + h
    int b = z / NH, h = z - b * NH;
    int rowBase = blockIdx.y * 128, colBase = blockIdx.x * 128;
    int tid = threadIdx.x;
    const float* qb = q + ((size_t)b * SEQ + rowBase) * D + h * HD;
    const float* kb = k + ((size_t)b * SEQ + colBase) * D + h * HD;
    int tx = tid & 15, ty = tid >> 4;
    float acc[8][8] = {};
    for (int kc = 0; kc < 64; kc += 32) {
        #pragma unroll
        for (int i = tid * 4; i < 128 * 32; i += 1024) {
            int r = i >> 5, c = i & 31;
            float4 tq = *(const float4*)(qb + (size_t)r * D + kc + c);
            Qs[c + 0][r] = tq.x; Qs[c + 1][r] = tq.y;
            Qs[c + 2][r] = tq.z; Qs[c + 3][r] = tq.w;
            float4 tk = *(const float4*)(kb + (size_t)r * D + kc + c);
            Ks[c + 0][r] = tk.x; Ks[c + 1][r] = tk.y;
            Ks[c + 2][r] = tk.z; Ks[c + 3][r] = tk.w;
        }
        __syncthreads();
        #pragma unroll
        for (int kk = 0; kk < 32; kk++) {
            float a[8], bb[8];
            #pragma unroll
            for (int i = 0; i < 8; i++) a[i]  = Qs[kk][ty * 8 + i];
            #pragma unroll
            for (int j = 0; j < 8; j++) bb[j] = Ks[kk][tx * 8 + j];
            #pragma unroll
            for (int i = 0; i < 8; i++)
                #pragma unroll
                for (int j = 0; j < 8; j++)
                    acc[i][j] = fmaf(a[i], bb[j], acc[i][j]);
        }
        __syncthreads();
    }
    float* eb = e + (size_t)z * SEQ * SEQ;
    #pragma unroll
    for (int i = 0; i < 8; i++) {
        size_t roff = (size_t)(rowBase + ty * 8 + i) * SEQ + colBase + tx * 8;
        #pragma unroll
        for (int j = 0; j < 8; j++)
            eb[roff + j] = acc[i][j] * 0.125f;
    }
}

// ---------------- row softmax over 2048, writes attention output -----------
__global__ void softmax_kernel(const float* __restrict__ e, float* __restrict__ attn)
{
    __shared__ float sh[8];
    size_t row = blockIdx.x;
    int t = threadIdx.x;
    const float4* er = (const float4*)(e + row * SEQ);
    float4 a = er[t], b = er[t + 256];
    float m = fmaxf(fmaxf(fmaxf(a.x, a.y), fmaxf(a.z, a.w)),
                    fmaxf(fmaxf(b.x, b.y), fmaxf(b.z, b.w)));
    #pragma unroll
    for (int o = 16; o; o >>= 1) m = fmaxf(m, __shfl_xor_sync(0xffffffffu, m, o));
    if ((t & 31) == 0) sh[t >> 5] = m;
    __syncthreads();
    if (t < 8) {
        m = sh[t];
        #pragma unroll
        for (int o = 4; o; o >>= 1) m = fmaxf(m, __shfl_xor_sync(0xffu, m, o));
        if (t == 0) sh[0] = m;
    }
    __syncthreads();
    m = sh[0];
    __syncthreads();
    a.x = expf(a.x - m); a.y = expf(a.y - m); a.z = expf(a.z - m); a.w = expf(a.w - m);
    b.x = expf(b.x - m); b.y = expf(b.y - m); b.z = expf(b.z - m); b.w = expf(b.w - m);
    float s = a.x + a.y + a.z + a.w + b.x + b.y + b.z + b.w;
    #pragma unroll
    for (int o = 16; o; o >>= 1) s += __shfl_xor_sync(0xffffffffu, s, o);
    if ((t & 31) == 0) sh[t >> 5] = s;
    __syncthreads();
    if (t < 8) {
        s = sh[t];
        #pragma unroll
        for (int o = 4; o; o >>= 1) s += __shfl_xor_sync(0xffu, s, o);
        if (t == 0) sh[0] = s;
    }
    __syncthreads();
    float inv = 1.0f / sh[0];
    a.x *= inv; a.y *= inv; a.z *= inv; a.w *= inv;
    b.x *= inv; b.y *= inv; b.z *= inv; b.w *= inv;
    float4* o4 = (float4*)(attn + row * SEQ);
    o4[t] = a; o4[t + 256] = b;
}

// ---------------- generic batched fp32 GEMM ---------------------------------
// C = A[M,K] @ B[K,N] (+bias) (GELU?) (+residual). All dims multiples of tiles.
// z batching: z1 = z/zmod, z0 = z%zmod; pointer += z1*s1 + z0*s0.
template<int BM, int BN, int BK, int TM, int TN, bool GELU>
__global__ void gemm_kernel(const float* __restrict__ A, int lda, size_t sA1, size_t sA0,
                            const float* __restrict__ Bp, int ldb, size_t sB1, size_t sB0,
                            float* __restrict__ C, int ldc, size_t sC1, size_t sC0,
                            const float* __restrict__ bias,
                            const float* __restrict__ res, int ldr,
                            int K, int zmod)
{
    constexpr int NT = (BM / TM) * (BN / TN);
    __shared__ float As[BK][BM];
    __shared__ float Bs[BK][BN];
    int z = blockIdx.z, z1 = z / zmod, z0 = z - z1 * zmod;
    A  += (size_t)z1 * sA1 + (size_t)z0 * sA0;
    Bp += (size_t)z1 * sB1 + (size_t)z0 * sB0;
    C  += (size_t)z1 * sC1 + (size_t)z0 * sC0;
    int tid = threadIdx.x;
    int row0 = blockIdx.y * BM, col0 = blockIdx.x * BN;
    int tx = tid % (BN / TN), ty = tid / (BN / TN);
    float acc[TM][TN] = {};
    for (int k0 = 0; k0 < K; k0 += BK) {
        #pragma unroll
        for (int i = tid * 4; i < BM * BK; i += NT * 4) {
            int r = i / BK, c = i % BK;
            float4 t4 = *(const float4*)(A + (size_t)(row0 + r) * lda + k0 + c);
            As[c + 0][r] = t4.x; As[c + 1][r] = t4.y;
            As[c + 2][r] = t4.z; As[c + 3][r] = t4.w;
        }
        #pragma unroll
        for (int i = tid * 4; i < BK * BN; i += NT * 4) {
            int r = i / BN, c = i % BN;
            *(float4*)(&Bs[r][c]) = *(const float4*)(Bp + (size_t)(k0 + r) * ldb + col0 + c);
        }
        __syncthreads();
        #pragma unroll
        for (int kk = 0; kk < BK; kk++) {
            float a[TM], bb[TN];
            #pragma unroll
            for (int i = 0; i < TM; i++) a[i]  = As[kk][ty * TM + i];
            #pragma unroll
            for (int j = 0; j < TN; j++) bb[j] = Bs[kk][tx * TN + j];
            #pragma unroll
            for (int i = 0; i < TM; i++)
                #pragma unroll
                for (int j = 0; j < TN; j++)
                    acc[i][j] = fmaf(a[i], bb[j], acc[i][j]);
        }
        __syncthreads();
    }
    #pragma unroll
    for (int i = 0; i < TM; i++) {
        int m = row0 + ty * TM + i;
        #pragma unroll
        for (int j = 0; j < TN; j++) {
            int n = col0 + tx * TN + j;
            float v = acc[i][j];
            if (bias) v += bias[n];
            if (GELU) v = 0.5f * v * (1.0f + erff(v * 0.7071067811865476f));
            if (res)  v += res[(size_t)m * ldr + n];
            C[(size_t)m * ldc + n] = v;
        }
    }
}

// ---------------- launch ----------------------------------------------------
extern "C" void kernel_launch(void* const* d_in, const int* in_sizes, int n_in,
                              void* d_out, int out_size)
{
    const float* x   = (const float*)d_in[0];
    const float* wq  = (const float*)d_in[1];  const float* bq  = (const float*)d_in[2];
    const float* wk  = (const float*)d_in[3];  const float* bk  = (const float*)d_in[4];
    const float* wv  = (const float*)d_in[5];  const float* bv  = (const float*)d_in[6];
    const float* wo  = (const float*)d_in[7];  const float* bo  = (const float*)d_in[8];
    const float* w1  = (const float*)d_in[9];  const float* b1  = (const float*)d_in[10];
    const float* w2  = (const float*)d_in[11]; const float* b2  = (const float*)d_in[12];
    const float* g1  = (const float*)d_in[13]; const float* be1 = (const float*)d_in[14];
    const float* g2  = (const float*)d_in[15]; const float* be2 = (const float*)d_in[16];

    float* out      = (float*)d_out;                  // x: [2,2048,768]
    float* attn_out = out + (size_t)NROW * D;         // attention: [2,12,2048,2048]

    float *h1, *q, *k, *v, *e, *ctx, *x2, *h2, *mlp;
    cudaGetSymbolAddress((void**)&h1,  g_h1);
    cudaGetSymbolAddress((void**)&q,   g_q);
    cudaGetSymbolAddress((void**)&k,   g_k);
    cudaGetSymbolAddress((void**)&v,   g_v);
    cudaGetSymbolAddress((void**)&e,   g_energy);
    cudaGetSymbolAddress((void**)&ctx, g_ctx);
    cudaGetSymbolAddress((void**)&x2,  g_x2);
    cudaGetSymbolAddress((void**)&h2,  g_h2);
    cudaGetSymbolAddress((void**)&mlp, g_mlp);

    // 1. LN1
    ln_kernel<<<NROW, 256>>>(x, g1, be1, h1);

    // 2. QKV projections (row-major [4096,768]; head h lives at cols h*64..)
    dim3 g768(D / 128, NROW / 128, 1);
    gemm_kernel<128,128,8,8,8,false><<<g768, 256>>>(h1, D, 0, 0, wq, D, 0, 0,
                                                    q,  D, 0, 0, bq, nullptr, 0, D, 1);
    gemm_kernel<128,128,8,8,8,false><<<g768, 256>>>(h1, D, 0, 0, wk, D, 0, 0,
                                                    k,  D, 0, 0, bk, nullptr, 0, D, 1);
    gemm_kernel<128,128,8,8,8,false><<<g768, 256>>>(h1, D, 0, 0, wv, D, 0, 0,
                                                    v,  D, 0, 0, bv, nullptr, 0, D, 1);

    // 3. energy = q k^T / 8   (per head)
    energy_kernel<<<dim3(SEQ / 128, SEQ / 128, NHEAD), 256>>>(q, k, e);

    // 4. attention = softmax(energy)  -> output
    softmax_kernel<<<(unsigned)((size_t)NHEAD * SEQ), 256>>>(e, attn_out);

    // 5. ctx = energy @ v  (reference bug: raw scaled energy, NOT softmax)
    gemm_kernel<128,64,8,8,4,false><<<dim3(1, SEQ / 128, NHEAD), 256>>>(
        e,   SEQ, (size_t)NH * SEQ * SEQ, (size_t)SEQ * SEQ,
        v,   D,   (size_t)SEQ * D,        (size_t)HD,
        ctx, D,   (size_t)SEQ * D,        (size_t)HD,
        nullptr, nullptr, 0, SEQ, NH);

    // 6. x2 = x + ctx @ wo + bo
    gemm_kernel<128,128,8,8,8,false><<<g768, 256>>>(ctx, D, 0, 0, wo, D, 0, 0,
                                                    x2,  D, 0, 0, bo, x, D, D, 1);

    // 7. LN2
    ln_kernel<<<NROW, 256>>>(x2, g2, be2, h2);

    // 8. mlp = gelu(h2 @ w1 + b1)
    gemm_kernel<128,128,8,8,8,true><<<dim3(F / 128, NROW / 128, 1), 256>>>(
        h2, D, 0, 0, w1, F, 0, 0, mlp, F, 0, 0, b1, nullptr, 0, D, 1);

    // 9. out = x2 + mlp @ w2 + b2
    gemm_kernel<128,128,8,8,8,false><<<g768, 256>>>(mlp, F, 0, 0, w2, D, 0, 0,
                                                    out, D, 0, 0, b2, x2, D, F, 1);
}

// round 3
// speedup vs baseline: 3.0430x; 3.0430x over previous
#include <cuda_runtime.h>
#include <math.h>
#include <stdint.h>

#define D    768
#define F    3072
#define SEQ  2048
#define BAT  2
#define NH   12
#define HD   64
#define NROW  (BAT*SEQ)   // 4096
#define NHEAD (BAT*NH)    // 24

// ---------------- scratch (device globals; allocations forbidden) -----------
__device__ float g_h1 [NROW*D];
__device__ float g_qkv[(size_t)NROW*3*D];
__device__ float g_wqkvT[3*D*D];
__device__ float g_bqkv[3*D];
__device__ float g_woT[D*D];
__device__ float g_w1T[D*F];
__device__ float g_w2T[D*F];
__device__ float g_vT [(size_t)NHEAD*HD*SEQ];
__device__ float g_e  [(size_t)NHEAD*SEQ*SEQ];   // 402 MB
__device__ float g_ctx[NROW*D];
__device__ float g_x2 [NROW*D];
__device__ float g_h2 [NROW*D];
__device__ float g_mlp[(size_t)NROW*F];

// ---------------- helpers ----------------------------------------------------
__device__ __forceinline__ uint32_t smem_u32(const void* p) {
    uint32_t a;
    asm("{ .reg .u64 t; cvta.to.shared.u64 t, %1; cvt.u32.u64 %0, t; }" : "=r"(a) : "l"(p));
    return a;
}
__device__ __forceinline__ float rna_tf32(float x) {
    float r;
    asm("cvt.rna.tf32.f32 %0, %1;" : "=f"(r) : "f"(x));
    return r;
}
__device__ __forceinline__ void mma8(float* d, const uint32_t* a, const uint32_t* b) {
    asm volatile(
        "mma.sync.aligned.m16n8k8.row.col.f32.tf32.tf32.f32 "
        "{%0,%1,%2,%3}, {%4,%5,%6,%7}, {%8,%9}, {%0,%1,%2,%3};"
        : "+f"(d[0]), "+f"(d[1]), "+f"(d[2]), "+f"(d[3])
        : "r"(a[0]), "r"(a[1]), "r"(a[2]), "r"(a[3]), "r"(b[0]), "r"(b[1]));
}
#define CP16(dst, src) asm volatile("cp.async.cg.shared.global [%0], [%1], 16;" :: "r"(dst), "l"(src) : "memory")
#define CP_COMMIT()    asm volatile("cp.async.commit_group;" ::: "memory")
#define CP_WAIT2()     asm volatile("cp.async.wait_group 2;" ::: "memory")

// ---------------- tf32 mma.sync GEMM -----------------------------------------
// C[M,N] = scale*(A[M,K] @ Bt[N,K]^T) (+bias) (GELU?) (round?) (+res)
// A, Bt K-major. CTA tile 128 x BN, 4 warps (2x2), warp tile 64 x BN/2, BK=32.
// Smem float layout per stage: A[4 kb][128 m][8 k] swizzled, then B likewise.
template<int BN, bool GELU, bool ROUND>
__global__ void __launch_bounds__(128, 2) mm_tf32(
    const float* __restrict__ A, int lda, size_t sA1, size_t sA0,
    const float* __restrict__ Bt, int ldb, size_t sB1, size_t sB0,
    float* __restrict__ C, int ldc, size_t sC1, size_t sC0,
    const float* __restrict__ bias, const float* __restrict__ res, int ldr,
    int K, int zmod, float scale)
{
    constexpr int S = 3;
    constexpr int WN = BN / 2;
    constexpr int NF = WN / 8;          // n-frags per warp
    constexpr int AF = 128 * 32;        // A floats per stage
    constexpr int BF = BN * 32;         // B floats per stage
    constexpr int STG = AF + BF;

    extern __shared__ float sm[];
    const uint32_t sb = smem_u32(sm);

    int tid = threadIdx.x, w = tid >> 5, lane = tid & 31;
    int wm = w >> 1, wn = w & 1;
    int q = lane >> 2, c4 = lane & 3;

    int z = blockIdx.z, z1 = z / zmod, z0 = z - z1 * zmod;
    A  += z1 * sA1 + z0 * sA0;
    Bt += z1 * sB1 + z0 * sB0;
    C  += z1 * sC1 + z0 * sC0;
    int row0 = blockIdx.y * 128, col0 = blockIdx.x * BN;

    const int nch = K >> 5;

    auto load_chunk = [&](int ch, int st) {
        const float* Ak = A + (size_t)row0 * lda + ch * 32;
        const float* Bk = Bt + (size_t)col0 * ldb + ch * 32;
        uint32_t base = sb + st * STG * 4;
        #pragma unroll 4
        for (int idx = tid; idx < (128 + BN) * 8; idx += 128) {
            int h = idx & 7, kb = h >> 1, half = h & 1;
            if (idx < 1024) {
                int m = idx >> 3;
                uint32_t fo = kb * 1024 + ((m * 8 + half * 4) ^ (m & 4));
                CP16(base + fo * 4, Ak + (size_t)m * lda + h * 4);
            } else {
                int n = (idx >> 3) - 128;
                uint32_t fo = AF + kb * (BN * 8) + ((n * 8 + half * 4) ^ (n & 4));
                CP16(base + fo * 4, Bk + (size_t)n * ldb + h * 4);
            }
        }
    };

    for (int cc = 0; cc < S; cc++) {
        if (cc < nch) load_chunk(cc, cc);
        CP_COMMIT();
    }

    float acc[4][NF][4];
    #pragma unroll
    for (int i = 0; i < 4; i++)
        #pragma unroll
        for (int j = 0; j < NF; j++)
            #pragma unroll
            for (int t = 0; t < 4; t++) acc[i][j][t] = 0.0f;

    const uint32_t* smu = (const uint32_t*)sm;

    for (int i = 0; i < nch; i++) {
        int st = i % S;
        CP_WAIT2();
        __syncthreads();
        const uint32_t* Au = smu + st * STG;
        const uint32_t* Bu = Au + AF;
        #pragma unroll
        for (int kb = 0; kb < 4; kb++) {
            uint32_t a[4][4], b[NF][2];
            #pragma unroll
            for (int mf = 0; mf < 4; mf++) {
                int r = wm * 64 + mf * 16 + q;
                a[mf][0] = Au[kb * 1024 + ((r * 8 + c4) ^ (r & 4))];
                a[mf][1] = Au[kb * 1024 + (((r + 8) * 8 + c4) ^ ((r + 8) & 4))];
                a[mf][2] = Au[kb * 1024 + ((r * 8 + c4 + 4) ^ (r & 4))];
                a[mf][3] = Au[kb * 1024 + (((r + 8) * 8 + c4 + 4) ^ ((r + 8) & 4))];
            }
            #pragma unroll
            for (int nf = 0; nf < NF; nf++) {
                int n = wn * WN + nf * 8 + q;
                b[nf][0] = Bu[kb * (BN * 8) + ((n * 8 + c4) ^ (n & 4))];
                b[nf][1] = Bu[kb * (BN * 8) + ((n * 8 + c4 + 4) ^ (n & 4))];
            }
            #pragma unroll
            for (int mf = 0; mf < 4; mf++)
                #pragma unroll
                for (int nf = 0; nf < NF; nf++)
                    mma8(acc[mf][nf], a[mf], b[nf]);
        }
        __syncthreads();
        int nx = i + S;
        if (nx < nch) load_chunk(nx, st);
        CP_COMMIT();
    }

    // epilogue: direct float2 stores
    #pragma unroll
    for (int mf = 0; mf < 4; mf++) {
        #pragma unroll
        for (int half = 0; half < 2; half++) {
            int m = row0 + wm * 64 + mf * 16 + q + half * 8;
            float* crow = C + (size_t)m * ldc;
            const float* rrow = res ? res + (size_t)m * ldr : nullptr;
            #pragma unroll
            for (int nf = 0; nf < NF; nf++) {
                int n = col0 + wn * WN + nf * 8 + c4 * 2;
                float v0 = acc[mf][nf][half * 2 + 0] * scale;
                float v1 = acc[mf][nf][half * 2 + 1] * scale;
                if (bias) { v0 += bias[n]; v1 += bias[n + 1]; }
                if (GELU) {
                    v0 = 0.5f * v0 * (1.0f + erff(v0 * 0.70710678118654752f));
                    v1 = 0.5f * v1 * (1.0f + erff(v1 * 0.70710678118654752f));
                }
                if (ROUND) { v0 = rna_tf32(v0); v1 = rna_tf32(v1); }
                if (res) { v0 += rrow[n]; v1 += rrow[n + 1]; }
                *(float2*)(crow + n) = make_float2(v0, v1);
            }
        }
    }
}

// ---------------- LayerNorm (rounds output to tf32) --------------------------
template<bool ROUND>
__global__ void ln_kernel(const float* __restrict__ x, const float* __restrict__ g,
                          const float* __restrict__ be, float* __restrict__ out)
{
    __shared__ float sh[16];
    int row = blockIdx.x, t = threadIdx.x;
    const float* xr = x + (size_t)row * D;
    float v0 = xr[t], v1 = xr[t + 256], v2 = xr[t + 512];
    float s = v0 + v1 + v2, sq = v0*v0 + v1*v1 + v2*v2;
    #pragma unroll
    for (int o = 16; o; o >>= 1) {
        s  += __shfl_down_sync(0xffffffffu, s,  o);
        sq += __shfl_down_sync(0xffffffffu, sq, o);
    }
    int lane = t & 31, w = t >> 5;
    if (lane == 0) { sh[w] = s; sh[8 + w] = sq; }
    __syncthreads();
    if (t < 8) {
        s = sh[t]; sq = sh[8 + t];
        #pragma unroll
        for (int o = 4; o; o >>= 1) {
            s  += __shfl_down_sync(0xffu, s,  o);
            sq += __shfl_down_sync(0xffu, sq, o);
        }
        if (t == 0) {
            float mu = s * (1.0f / 768.0f);
            float var = sq * (1.0f / 768.0f) - mu * mu;
            sh[0] = mu; sh[1] = rsqrtf(var + 1e-5f);
        }
    }
    __syncthreads();
    float mu = sh[0], r = sh[1];
    float* orow = out + (size_t)row * D;
    float o0 = (v0 - mu) * r * g[t]       + be[t];
    float o1 = (v1 - mu) * r * g[t + 256] + be[t + 256];
    float o2 = (v2 - mu) * r * g[t + 512] + be[t + 512];
    if (ROUND) { o0 = rna_tf32(o0); o1 = rna_tf32(o1); o2 = rna_tf32(o2); }
    orow[t] = o0; orow[t + 256] = o1; orow[t + 512] = o2;
}

// ---------------- softmax over rows of 2048 (writes attention output) --------
__global__ void softmax_kernel(const float* __restrict__ e, float* __restrict__ attn)
{
    __shared__ float sh[8];
    size_t row = blockIdx.x;
    int t = threadIdx.x;
    const float4* er = (const float4*)(e + row * SEQ);
    float4 a = er[t], b = er[t + 256];
    float m = fmaxf(fmaxf(fmaxf(a.x, a.y), fmaxf(a.z, a.w)),
                    fmaxf(fmaxf(b.x, b.y), fmaxf(b.z, b.w)));
    #pragma unroll
    for (int o = 16; o; o >>= 1) m = fmaxf(m, __shfl_xor_sync(0xffffffffu, m, o));
    if ((t & 31) == 0) sh[t >> 5] = m;
    __syncthreads();
    if (t < 8) {
        m = sh[t];
        #pragma unroll
        for (int o = 4; o; o >>= 1) m = fmaxf(m, __shfl_xor_sync(0xffu, m, o));
        if (t == 0) sh[0] = m;
    }
    __syncthreads();
    m = sh[0];
    __syncthreads();
    a.x = expf(a.x - m); a.y = expf(a.y - m); a.z = expf(a.z - m); a.w = expf(a.w - m);
    b.x = expf(b.x - m); b.y = expf(b.y - m); b.z = expf(b.z - m); b.w = expf(b.w - m);
    float s = a.x + a.y + a.z + a.w + b.x + b.y + b.z + b.w;
    #pragma unroll
    for (int o = 16; o; o >>= 1) s += __shfl_xor_sync(0xffffffffu, s, o);
    if ((t & 31) == 0) sh[t >> 5] = s;
    __syncthreads();
    if (t < 8) {
        s = sh[t];
        #pragma unroll
        for (int o = 4; o; o >>= 1) s += __shfl_xor_sync(0xffu, s, o);
        if (t == 0) sh[0] = s;
    }
    __syncthreads();
    float inv = 1.0f / sh[0];
    a.x *= inv; a.y *= inv; a.z *= inv; a.w *= inv;
    b.x *= inv; b.y *= inv; b.z *= inv; b.w *= inv;
    float4* o4 = (float4*)(attn + row * SEQ);
    o4[t] = a; o4[t + 256] = b;
}

// ---------------- weight transpose + round -----------------------------------
__global__ void transpose_round(const float* __restrict__ in, float* __restrict__ out,
                                int K, int N)
{
    __shared__ float tile[32][33];
    int k0 = blockIdx.y * 32, n0 = blockIdx.x * 32;
    int tx = threadIdx.x, ty = threadIdx.y;
    #pragma unroll
    for (int i = ty; i < 32; i += 8)
        tile[i][tx] = in[(size_t)(k0 + i) * N + n0 + tx];
    __syncthreads();
    #pragma unroll
    for (int i = ty; i < 32; i += 8)
        out[(size_t)(n0 + i) * K + k0 + tx] = rna_tf32(tile[tx][i]);
}

// per-head v transpose: vT[z][n][k] = qkv[(b*SEQ+k)*2304 + 1536 + h*64 + n]
__global__ void vtrans_kernel(const float* __restrict__ qkv, float* __restrict__ vT)
{
    __shared__ float tile[32][33];
    int z = blockIdx.z, b = z / NH, h = z - b * NH;
    int k0 = blockIdx.x * 32, n0 = blockIdx.y * 32;
    int tx = threadIdx.x, ty = threadIdx.y;
    const float* src = qkv + (size_t)b * SEQ * (3 * D) + 2 * D + h * HD;
    #pragma unroll
    for (int i = ty; i < 32; i += 8)
        tile[i][tx] = src[(size_t)(k0 + i) * (3 * D) + n0 + tx];
    __syncthreads();
    float* dst = vT + (size_t)z * HD * SEQ;
    #pragma unroll
    for (int i = ty; i < 32; i += 8)
        dst[(size_t)(n0 + i) * SEQ + k0 + tx] = tile[tx][i];
}

__global__ void pack_bias(const float* bq, const float* bk, const float* bv, float* o)
{
    int j = blockIdx.x * 256 + threadIdx.x;
    if (j < 3 * D) o[j] = (j < D) ? bq[j] : (j < 2 * D) ? bk[j - D] : bv[j - 2 * D];
}

// ---------------- launch ------------------------------------------------------
extern "C" void kernel_launch(void* const* d_in, const int* in_sizes, int n_in,
                              void* d_out, int out_size)
{
    const float* x   = (const float*)d_in[0];
    const float* wq  = (const float*)d_in[1];  const float* bq  = (const float*)d_in[2];
    const float* wk  = (const float*)d_in[3];  const float* bk  = (const float*)d_in[4];
    const float* wv  = (const float*)d_in[5];  const float* bv  = (const float*)d_in[6];
    const float* wo  = (const float*)d_in[7];  const float* bo  = (const float*)d_in[8];
    const float* w1  = (const float*)d_in[9];  const float* b1  = (const float*)d_in[10];
    const float* w2  = (const float*)d_in[11]; const float* b2  = (const float*)d_in[12];
    const float* g1  = (const float*)d_in[13]; const float* be1 = (const float*)d_in[14];
    const float* g2  = (const float*)d_in[15]; const float* be2 = (const float*)d_in[16];

    float* out      = (float*)d_out;
    float* attn_out = out + (size_t)NROW * D;

    float *h1, *qkv, *wqkvT, *bqkv, *woT, *w1T, *w2T, *vT, *e, *ctx, *x2, *h2, *mlp;
    cudaGetSymbolAddress((void**)&h1,    g_h1);
    cudaGetSymbolAddress((void**)&qkv,   g_qkv);
    cudaGetSymbolAddress((void**)&wqkvT, g_wqkvT);
    cudaGetSymbolAddress((void**)&bqkv,  g_bqkv);
    cudaGetSymbolAddress((void**)&woT,   g_woT);
    cudaGetSymbolAddress((void**)&w1T,   g_w1T);
    cudaGetSymbolAddress((void**)&w2T,   g_w2T);
    cudaGetSymbolAddress((void**)&vT,    g_vT);
    cudaGetSymbolAddress((void**)&e,     g_e);
    cudaGetSymbolAddress((void**)&ctx,   g_ctx);
    cudaGetSymbolAddress((void**)&x2,    g_x2);
    cudaGetSymbolAddress((void**)&h2,    g_h2);
    cudaGetSymbolAddress((void**)&mlp,   g_mlp);

    const int SM128 = 3 * (128 * 32 + 128 * 32) * 4;   // 96 KB
    const int SM64  = 3 * (128 * 32 + 64 * 32) * 4;    // 72 KB
    cudaFuncSetAttribute(mm_tf32<128, false, true>,  cudaFuncAttributeMaxDynamicSharedMemorySize, SM128);
    cudaFuncSetAttribute(mm_tf32<128, false, false>, cudaFuncAttributeMaxDynamicSharedMemorySize, SM128);
    cudaFuncSetAttribute(mm_tf32<128, true,  true>,  cudaFuncAttributeMaxDynamicSharedMemorySize, SM128);
    cudaFuncSetAttribute(mm_tf32<64,  false, true>,  cudaFuncAttributeMaxDynamicSharedMemorySize, SM64);

    dim3 tb(32, 8);
    transpose_round<<<dim3(D / 32, D / 32), tb>>>(wq, wqkvT,             D, D);
    transpose_round<<<dim3(D / 32, D / 32), tb>>>(wk, wqkvT + D * D,     D, D);
    transpose_round<<<dim3(D / 32, D / 32), tb>>>(wv, wqkvT + 2 * D * D, D, D);
    transpose_round<<<dim3(D / 32, D / 32), tb>>>(wo, woT, D, D);
    transpose_round<<<dim3(F / 32, D / 32), tb>>>(w1, w1T, D, F);
    transpose_round<<<dim3(D / 32, F / 32), tb>>>(w2, w2T, F, D);
    pack_bias<<<(3 * D + 255) / 256, 256>>>(bq, bk, bv, bqkv);

    // 1. LN1 (rounded: feeds QKV GEMM)
    ln_kernel<true><<<NROW, 256>>>(x, g1, be1, h1);

    // 2. fused QKV: qkv[4096,2304] = h1 @ [wq|wk|wv] + bias  (rounded)
    mm_tf32<128, false, true><<<dim3(3 * D / 128, NROW / 128, 1), 128, SM128>>>(
        h1, D, 0, 0, wqkvT, D, 0, 0, qkv, 3 * D, 0, 0, bqkv, nullptr, 0, D, 1, 1.0f);

    // 3. per-head v transpose -> vT[24][64][2048]
    vtrans_kernel<<<dim3(SEQ / 32, HD / 32, NHEAD), tb>>>(qkv, vT);

    // 4. energy = q k^T / 8  (rounded; feeds softmax + ctx)
    mm_tf32<128, false, true><<<dim3(SEQ / 128, SEQ / 128, NHEAD), 128, SM128>>>(
        qkv,     3 * D, (size_t)SEQ * 3 * D, HD,
        qkv + D, 3 * D, (size_t)SEQ * 3 * D, HD,
        e, SEQ, (size_t)NH * SEQ * SEQ, (size_t)SEQ * SEQ,
        nullptr, nullptr, 0, HD, NH, 0.125f);

    // 5. attention = softmax(energy)
    softmax_kernel<<<(unsigned)((size_t)NHEAD * SEQ), 256>>>(e, attn_out);

    // 6. ctx = energy @ v  (reference bug preserved; rounded: feeds Wo)
    mm_tf32<64, false, true><<<dim3(1, SEQ / 128, NHEAD), 128, SM64>>>(
        e,  SEQ, (size_t)NH * SEQ * SEQ, (size_t)SEQ * SEQ,
        vT, SEQ, (size_t)NH * HD * SEQ,  (size_t)HD * SEQ,
        ctx, D, (size_t)SEQ * D, HD,
        nullptr, nullptr, 0, SEQ, NH, 1.0f);

    // 7. x2 = x + ctx @ wo + bo
    mm_tf32<128, false, false><<<dim3(D / 128, NROW / 128, 1), 128, SM128>>>(
        ctx, D, 0, 0, woT, D, 0, 0, x2, D, 0, 0, bo, x, D, D, 1, 1.0f);

    // 8. LN2 (rounded: feeds MLP1)
    ln_kernel<true><<<NROW, 256>>>(x2, g2, be2, h2);

    // 9. mlp = gelu(h2 @ w1 + b1)  (rounded: feeds MLP2)
    mm_tf32<128, true, true><<<dim3(F / 128, NROW / 128, 1), 128, SM128>>>(
        h2, D, 0, 0, w1T, D, 0, 0, mlp, F, 0, 0, b1, nullptr, 0, D, 1, 1.0f);

    // 10. out = x2 + mlp @ w2 + b2
    mm_tf32<128, false, false><<<dim3(D / 128, NROW / 128, 1), 128, SM128>>>(
        mlp, F, 0, 0, w2T, F, 0, 0, out, D, 0, 0, b2, x2, D, F, 1, 1.0f);
}